// round 5
// baseline (speedup 1.0000x reference)
#include <cuda_runtime.h>
#include <cstdint>

// ---------------------------------------------------------------------------
// ActivityDecaySNN: 3-layer LIF SNN forward. T=50, B=512, 784->800->800->10.
// BITWISE CONSTRAINT: outputs match only if currents reproduce the reference's
// ascending-k fp32 FMA chain per element. fma.rn.f32x2 = 2 independent
// fma.rn.f32 (bitwise identical) -> used to double FLOP/issue vs scalar FFMA.
// d_out: out[512*10] | s1r[50*512*800] | s2r[50*512*800] | s3r[50*512*10]
// ---------------------------------------------------------------------------

#define T_STEPS 50
#define BATCH   512
#define DIN     784
#define HID     800
#define NOUT    10
#define M_ROWS  (T_STEPS * BATCH)   // 25600

__device__ float g_c1[(size_t)M_ROWS * HID];
__device__ float g_c2[(size_t)M_ROWS * HID];
__device__ float g_c3[(size_t)M_ROWS * NOUT];

typedef unsigned long long ull;

// ============================ asm helpers ==================================
__device__ __forceinline__ void fma2(ull& d, ull a, ull b) {
    asm("fma.rn.f32x2 %0, %1, %2, %0;" : "+l"(d) : "l"(a), "l"(b));
}
__device__ __forceinline__ void lds_v2u64(ull& a, ull& b, uint32_t addr) {
    asm volatile("ld.shared.v2.u64 {%0,%1}, [%2];" : "=l"(a), "=l"(b) : "r"(addr));
}
__device__ __forceinline__ void sts64_dup(uint32_t addr, float v) {
    asm volatile("st.shared.v2.f32 [%0], {%1,%2};" :: "r"(addr), "f"(v), "f"(v));
}
__device__ __forceinline__ void sts32(uint32_t addr, float v) {
    asm volatile("st.shared.f32 [%0], %1;" :: "r"(addr), "f"(v));
}
__device__ __forceinline__ float lo32(ull v) { return __uint_as_float((uint32_t)v); }
__device__ __forceinline__ float hi32(ull v) { return __uint_as_float((uint32_t)(v >> 32)); }

// ===========================================================================
// SGEMM (NT) with packed f32x2 FMA:
//   C[M,N] = A[M,K] @ W[N,K]^T + bias[N],  K padded to KP=800 (BK=32, 25 tiles)
// BM=BN=128, 256 threads, 8x8 microtile (as 8x4 f32x2 pairs).
// Smem: A stored DUPLICATED ({a,a} pairs, row 1040B) so ld.shared.v2.u64
// yields broadcast pairs directly; W rows 528B. Double-buffered, register-
// staged prefetch, one __syncthreads per tile.
// ===========================================================================
#define BKT    32
#define NTILE  25                    // 800 / 32
#define AROWB  1040                  // bytes per A2 smem row (2*128*4 + 16 pad)
#define WROWB  528                   // bytes per W  smem row (128*4 + 16 pad)
#define ABUFB  (BKT * AROWB)         // 33280
#define WBUFB  (BKT * WROWB)         // 16896
#define SMEMB  (2 * ABUFB + 2 * WBUFB)  // 100352 bytes

__global__ __launch_bounds__(256, 2)
void sgemm_f32x2(const float* __restrict__ A, const float* __restrict__ W,
                 const float* __restrict__ bias, float* __restrict__ C,
                 int M, int N, int K)
{
    extern __shared__ float smraw[];
    const uint32_t smb = (uint32_t)__cvta_generic_to_shared(smraw);

    const int tid = threadIdx.x;
    const int tx  = tid & 15;            // n-direction (8 cols = 4 pairs)
    const int ty  = tid >> 4;            // m-direction (8 rows)
    const int m0  = blockIdx.y * 128;
    const int n0  = blockIdx.x * 128;

    const int ldColK = (tid & 7) * 4;    // k-quad base within tile
    const int ldRow  = tid >> 3;         // row 0..31 (4 passes x 32 rows)

    ull acc[8][4];
    #pragma unroll
    for (int i = 0; i < 8; ++i)
        #pragma unroll
        for (int j = 0; j < 4; ++j) acc[i][j] = 0ull;

    const float4 z4 = make_float4(0.f, 0.f, 0.f, 0.f);

    // ---- prologue: stage tile 0 into buffer 0 ----
    {
        #pragma unroll
        for (int p = 0; p < 4; ++p) {
            const int r  = ldRow + p * 32;
            const int gk = ldColK;
            const float4 av = (gk < K)
                ? *reinterpret_cast<const float4*>(A + (size_t)(m0 + r) * K + gk) : z4;
            const int wn = n0 + r;
            const float4 wv = (wn < N && gk < K)
                ? *reinterpret_cast<const float4*>(W + (size_t)wn * K + gk) : z4;
            #pragma unroll
            for (int q = 0; q < 4; ++q) {
                sts64_dup(smb + (ldColK + q) * AROWB + r * 8, (&av.x)[q]);
                sts32(smb + 2 * ABUFB + (ldColK + q) * WROWB + r * 4, (&wv.x)[q]);
            }
        }
    }
    __syncthreads();

    for (int t = 0; t < NTILE; ++t) {
        const int  buf     = t & 1;
        const int  nb      = buf ^ 1;
        const bool hasNext = (t + 1 < NTILE);
        const int  kn      = (t + 1) * BKT;

        const uint32_t ab  = smb + buf * ABUFB;
        const uint32_t wb  = smb + 2 * ABUFB + buf * WBUFB;
        const uint32_t abn = smb + nb * ABUFB;
        const uint32_t wbn = smb + 2 * ABUFB + nb * WBUFB;

        float4 pa[2], pw[2];

        // -- prefetch half 1 (passes 0,1) --
        if (hasNext) {
            const int gk = kn + ldColK;
            #pragma unroll
            for (int p = 0; p < 2; ++p) {
                const int r = ldRow + p * 32;
                pa[p] = (gk < K)
                    ? *reinterpret_cast<const float4*>(A + (size_t)(m0 + r) * K + gk) : z4;
                const int wn = n0 + r;
                pw[p] = (wn < N && gk < K)
                    ? *reinterpret_cast<const float4*>(W + (size_t)wn * K + gk) : z4;
            }
        }

        // -- compute kk 0..15 --
        #pragma unroll 4
        for (int kk = 0; kk < 16; ++kk) {
            ull afd[8], wfd[4];
            const uint32_t aadr = ab + kk * AROWB + ty * 64;
            lds_v2u64(afd[0], afd[1], aadr);
            lds_v2u64(afd[2], afd[3], aadr + 16);
            lds_v2u64(afd[4], afd[5], aadr + 32);
            lds_v2u64(afd[6], afd[7], aadr + 48);
            const uint32_t wadr = wb + kk * WROWB + tx * 16;
            lds_v2u64(wfd[0], wfd[1], wadr);
            lds_v2u64(wfd[2], wfd[3], wadr + 256);
            #pragma unroll
            for (int i = 0; i < 8; ++i)
                #pragma unroll
                for (int j = 0; j < 4; ++j)
                    fma2(acc[i][j], afd[i], wfd[j]);
        }

        // -- store half 1, prefetch half 2 (passes 2,3) --
        if (hasNext) {
            #pragma unroll
            for (int p = 0; p < 2; ++p) {
                const int r = ldRow + p * 32;
                #pragma unroll
                for (int q = 0; q < 4; ++q) {
                    sts64_dup(abn + (ldColK + q) * AROWB + r * 8, (&pa[p].x)[q]);
                    sts32(wbn + (ldColK + q) * WROWB + r * 4, (&pw[p].x)[q]);
                }
            }
            const int gk = kn + ldColK;
            #pragma unroll
            for (int p = 0; p < 2; ++p) {
                const int r = ldRow + (2 + p) * 32;
                pa[p] = (gk < K)
                    ? *reinterpret_cast<const float4*>(A + (size_t)(m0 + r) * K + gk) : z4;
                const int wn = n0 + r;
                pw[p] = (wn < N && gk < K)
                    ? *reinterpret_cast<const float4*>(W + (size_t)wn * K + gk) : z4;
            }
        }

        // -- compute kk 16..31 --
        #pragma unroll 4
        for (int kk = 16; kk < 32; ++kk) {
            ull afd[8], wfd[4];
            const uint32_t aadr = ab + kk * AROWB + ty * 64;
            lds_v2u64(afd[0], afd[1], aadr);
            lds_v2u64(afd[2], afd[3], aadr + 16);
            lds_v2u64(afd[4], afd[5], aadr + 32);
            lds_v2u64(afd[6], afd[7], aadr + 48);
            const uint32_t wadr = wb + kk * WROWB + tx * 16;
            lds_v2u64(wfd[0], wfd[1], wadr);
            lds_v2u64(wfd[2], wfd[3], wadr + 256);
            #pragma unroll
            for (int i = 0; i < 8; ++i)
                #pragma unroll
                for (int j = 0; j < 4; ++j)
                    fma2(acc[i][j], afd[i], wfd[j]);
        }

        // -- store half 2, publish --
        if (hasNext) {
            #pragma unroll
            for (int p = 0; p < 2; ++p) {
                const int r = ldRow + (2 + p) * 32;
                #pragma unroll
                for (int q = 0; q < 4; ++q) {
                    sts64_dup(abn + (ldColK + q) * AROWB + r * 8, (&pa[p].x)[q]);
                    sts32(wbn + (ldColK + q) * WROWB + r * 4, (&pw[p].x)[q]);
                }
            }
            __syncthreads();
        }
    }

    // ---- epilogue: unpack pairs, add bias, store (bitwise same as R4) ----
    #pragma unroll
    for (int i = 0; i < 8; ++i) {
        const int m = m0 + ty * 8 + i;
        {
            const int n = n0 + tx * 4;
            if (n < N) {
                float4 v;
                v.x = lo32(acc[i][0]) + bias[n + 0];
                v.y = hi32(acc[i][0]) + bias[n + 1];
                v.z = lo32(acc[i][1]) + bias[n + 2];
                v.w = hi32(acc[i][1]) + bias[n + 3];
                *reinterpret_cast<float4*>(C + (size_t)m * N + n) = v;
            }
        }
        {
            const int n = n0 + 64 + tx * 4;
            if (n < N) {
                float4 v;
                v.x = lo32(acc[i][2]) + bias[n + 0];
                v.y = hi32(acc[i][2]) + bias[n + 1];
                v.z = lo32(acc[i][3]) + bias[n + 2];
                v.w = hi32(acc[i][3]) + bias[n + 3];
                *reinterpret_cast<float4*>(C + (size_t)m * N + n) = v;
            }
        }
    }
}

// ===========================================================================
// LIF recurrence, float4-vectorized (component-wise, bitwise identical).
// ===========================================================================
__global__ void lif_kernel4(const float4* __restrict__ cur,
                            float4* __restrict__ spk,
                            const float* __restrict__ beta_ptr, int BH4)
{
    const int idx = blockIdx.x * blockDim.x + threadIdx.x;
    if (idx >= BH4) return;
    const float beta = fminf(fmaxf(beta_ptr[0], 0.0f), 1.0f);
    float4 mem = make_float4(0.f, 0.f, 0.f, 0.f);
    float4 rst = make_float4(0.f, 0.f, 0.f, 0.f);
    #pragma unroll
    for (int t = 0; t < T_STEPS; ++t) {
        const float4 c = cur[(size_t)t * BH4 + idx];
        float4 s;
        mem.x = beta * mem.x + c.x - rst.x; s.x = (mem.x - 1.0f > 0.0f) ? 1.0f : 0.0f;
        mem.y = beta * mem.y + c.y - rst.y; s.y = (mem.y - 1.0f > 0.0f) ? 1.0f : 0.0f;
        mem.z = beta * mem.z + c.z - rst.z; s.z = (mem.z - 1.0f > 0.0f) ? 1.0f : 0.0f;
        mem.w = beta * mem.w + c.w - rst.w; s.w = (mem.w - 1.0f > 0.0f) ? 1.0f : 0.0f;
        spk[(size_t)t * BH4 + idx] = s;
        rst = s;
    }
}

__global__ __launch_bounds__(256)
void gemm3_kernel(const float* __restrict__ S2, const float* __restrict__ W3,
                  const float* __restrict__ b3, float* __restrict__ C3, int M)
{
    __shared__ float w3s[NOUT * HID];
    for (int i = threadIdx.x; i < NOUT * HID; i += 256) w3s[i] = W3[i];
    __syncthreads();

    const int warp = threadIdx.x >> 5;
    const int lane = threadIdx.x & 31;
    const int row  = blockIdx.x * 8 + warp;
    if (row >= M) return;

    const float* s = S2 + (size_t)row * HID;
    float sv[HID / 32];
    #pragma unroll
    for (int i = 0; i < HID / 32; ++i) sv[i] = s[lane + i * 32];

    float accv[NOUT];
    #pragma unroll
    for (int o = 0; o < NOUT; ++o) {
        float a = 0.0f;
        #pragma unroll
        for (int i = 0; i < HID / 32; ++i)
            a += sv[i] * w3s[o * HID + lane + i * 32];
        accv[o] = a;
    }
    #pragma unroll
    for (int o = 0; o < NOUT; ++o) {
        float v = accv[o];
        #pragma unroll
        for (int off = 16; off > 0; off >>= 1)
            v += __shfl_down_sync(0xffffffffu, v, off);
        if (lane == 0) C3[(size_t)row * NOUT + o] = v + b3[o];
    }
}

__global__ void lif3_kernel(const float* __restrict__ C3,
                            float* __restrict__ s3r, float* __restrict__ out,
                            const float* __restrict__ beta_ptr)
{
    const int idx = blockIdx.x * blockDim.x + threadIdx.x;
    if (idx >= BATCH * NOUT) return;
    const float beta = fminf(fmaxf(beta_ptr[0], 0.0f), 1.0f);
    float mem = 0.0f, rst = 0.0f, sum = 0.0f;
    #pragma unroll
    for (int t = 0; t < T_STEPS; ++t) {
        const float c = C3[(size_t)t * BATCH * NOUT + idx];
        mem = beta * mem + c - rst;
        const float s = (mem - 1.0f > 0.0f) ? 1.0f : 0.0f;
        s3r[(size_t)t * BATCH * NOUT + idx] = s;
        sum += s;
        rst = s;
    }
    out[idx] = sum;
}

// ===========================================================================
extern "C" void kernel_launch(void* const* d_in, const int* in_sizes, int n_in,
                              void* d_out, int out_size)
{
    const float* x     = (const float*)d_in[0];
    const float* W1    = (const float*)d_in[1];
    const float* b1    = (const float*)d_in[2];
    const float* W2    = (const float*)d_in[3];
    const float* b2    = (const float*)d_in[4];
    const float* W3    = (const float*)d_in[5];
    const float* b3    = (const float*)d_in[6];
    const float* beta1 = (const float*)d_in[7];
    const float* beta2 = (const float*)d_in[8];
    const float* beta3 = (const float*)d_in[9];

    float* out = (float*)d_out;
    float* s1r = out + (size_t)BATCH * NOUT;
    float* s2r = s1r + (size_t)M_ROWS * HID;
    float* s3r = s2r + (size_t)M_ROWS * HID;

    float *c1, *c2, *c3;
    cudaGetSymbolAddress((void**)&c1, g_c1);
    cudaGetSymbolAddress((void**)&c2, g_c2);
    cudaGetSymbolAddress((void**)&c3, g_c3);

    static bool attr_set = false;
    if (!attr_set) {
        cudaFuncSetAttribute(sgemm_f32x2, cudaFuncAttributeMaxDynamicSharedMemorySize, SMEMB);
        attr_set = true;
    }

    const int BH  = BATCH * HID;   // 409600
    const int BH4 = BH / 4;        // 102400
    const dim3 grid((HID + 127) / 128, M_ROWS / 128);

    // 1) C1 = X @ W1^T + b1   (K=784, padded to 800 inside)
    sgemm_f32x2<<<grid, 256, SMEMB>>>(x, W1, b1, c1, M_ROWS, HID, DIN);

    // 2) LIF1 -> s1r
    lif_kernel4<<<(BH4 + 255) / 256, 256>>>((const float4*)c1, (float4*)s1r, beta1, BH4);

    // 3) C2 = S1 @ W2^T + b2  (K=800)
    sgemm_f32x2<<<grid, 256, SMEMB>>>(s1r, W2, b2, c2, M_ROWS, HID, HID);

    // 4) LIF2 -> s2r
    lif_kernel4<<<(BH4 + 255) / 256, 256>>>((const float4*)c2, (float4*)s2r, beta2, BH4);

    // 5) C3 = S2 @ W3^T + b3
    gemm3_kernel<<<M_ROWS / 8, 256>>>(s2r, W3, b3, c3, M_ROWS);

    // 6) LIF3 + sum
    lif3_kernel<<<(BATCH * NOUT + 255) / 256, 256>>>(c3, s3r, out, beta3);
}

// round 6
// speedup vs baseline: 1.4534x; 1.4534x over previous
#include <cuda_runtime.h>
#include <cstdint>

// ---------------------------------------------------------------------------
// ActivityDecaySNN: 3-layer LIF SNN forward. T=50, B=512, 784->800->800->10.
// BITWISE CONSTRAINT: currents must reproduce the reference's ascending-k fp32
// FMA chain per element (R1/R3/R4 evidence). GEMM1: scalar SIMT SGEMM (at the
// FFMA issue roofline). GEMM2: input is BINARY spikes -> skipping zero terms
// is bitwise exact -> sparse ascending gather of W2T rows (warp-uniform lists).
// d_out: out[512*10] | s1r[50*512*800] | s2r[50*512*800] | s3r[50*512*10]
// ---------------------------------------------------------------------------

#define T_STEPS 50
#define BATCH   512
#define DIN     784
#define HID     800
#define NOUT    10
#define M_ROWS  (T_STEPS * BATCH)   // 25600

__device__ float  g_c1[(size_t)M_ROWS * HID];
__device__ float  g_c2[(size_t)M_ROWS * HID];
__device__ float  g_c3[(size_t)M_ROWS * NOUT];
__device__ float  g_w2t[(size_t)HID * HID];          // W2 transposed [k][n]
__device__ unsigned short g_klist[(size_t)M_ROWS * HID];  // per-row active k's
__device__ int    g_kcount[M_ROWS];

// ===========================================================================
// W2 transpose: W2T[k][n] = W2[n][k]. 32x32 tiles.
// ===========================================================================
__global__ void transpose_w2(const float* __restrict__ W, float* __restrict__ WT)
{
    __shared__ float t[32][33];
    const int bx = blockIdx.x * 32, by = blockIdx.y * 32;
    #pragma unroll
    for (int r = 0; r < 4; ++r)
        t[threadIdx.y + r * 8][threadIdx.x] =
            W[(size_t)(by + threadIdx.y + r * 8) * HID + bx + threadIdx.x];
    __syncthreads();
    #pragma unroll
    for (int r = 0; r < 4; ++r)
        WT[(size_t)(bx + threadIdx.y + r * 8) * HID + by + threadIdx.x] =
            t[threadIdx.x][threadIdx.y + r * 8];
}

// ===========================================================================
// Build ascending active-k lists per row m (one warp per row, ballot-compact).
// ===========================================================================
__global__ __launch_bounds__(256)
void build_klist(const float* __restrict__ spk,
                 unsigned short* __restrict__ klist, int* __restrict__ kcount)
{
    const int m    = blockIdx.x * 8 + (threadIdx.x >> 5);
    const int lane = threadIdx.x & 31;
    const float* row = spk + (size_t)m * HID;
    unsigned short* kl = klist + (size_t)m * HID;
    int base = 0;
    #pragma unroll
    for (int c = 0; c < HID / 32; ++c) {
        const int k = c * 32 + lane;
        const bool act = row[k] > 0.5f;
        const unsigned mask = __ballot_sync(0xffffffffu, act);
        if (act) kl[base + __popc(mask & ((1u << lane) - 1u))] = (unsigned short)k;
        base += __popc(mask);
    }
    if (lane == 0) kcount[m] = base;
}

// ===========================================================================
// Sparse GEMM2: C2[m,n] = b2[n] + sum_{k active(m), ascending} W2T[k][n]
// Block: 128 m x 128 n; 8 warps, warp owns 16 consecutive m (uniform k-list
// per warp -> no divergence). W2T staged in 80-row k-tiles (40 KB smem).
// ===========================================================================
#define SBK 80
#define NBLK ((HID + 127) / 128)    // 7

__global__ __launch_bounds__(256, 2)
void gemm2_sparse(const unsigned short* __restrict__ klist,
                  const int* __restrict__ kcount,
                  const float* __restrict__ WT,
                  const float* __restrict__ bias, float* __restrict__ C)
{
    __shared__ float wt[SBK * 128];    // 40 KB

    const int tid   = threadIdx.x;
    const int warp  = tid >> 5;
    const int lane  = tid & 31;
    const int n0    = blockIdx.x * 128;
    const int m0w   = blockIdx.y * 128 + warp * 16;   // warp's first m-row
    const int lane4 = lane * 4;

    const unsigned short* klw = klist + (size_t)m0w * HID;

    float acc[16][4];
    int   cur[16], cnt[16];
    #pragma unroll
    for (int mi = 0; mi < 16; ++mi) {
        cur[mi] = 0;
        cnt[mi] = kcount[m0w + mi];
        #pragma unroll
        for (int j = 0; j < 4; ++j) acc[mi][j] = 0.0f;
    }

    for (int k0 = 0; k0 < HID; k0 += SBK) {
        __syncthreads();   // protect previous tile from overwrite
        // ---- stage W2T[k0:k0+80, n0:n0+128) ----
        #pragma unroll
        for (int p = 0; p < SBK * 32 / 256; ++p) {        // 10 passes
            const int i   = tid + p * 256;
            const int row = i >> 5, c4 = i & 31;
            const int gn  = n0 + c4 * 4;
            const float4 v = (gn < HID)
                ? *reinterpret_cast<const float4*>(WT + (size_t)(k0 + row) * HID + gn)
                : make_float4(0.f, 0.f, 0.f, 0.f);
            *reinterpret_cast<float4*>(&wt[row * 128 + c4 * 4]) = v;
        }
        __syncthreads();

        const int kend = k0 + SBK;
        #pragma unroll
        for (int mi = 0; mi < 16; ++mi) {
            int c = cur[mi];
            const int ce = cnt[mi];
            const unsigned short* klp = klw + mi * HID;
            while (c < ce) {
                const int k = __ldg(klp + c);
                if (k >= kend) break;
                const float4 wv = *reinterpret_cast<const float4*>(
                    &wt[(k - k0) * 128 + lane4]);
                acc[mi][0] += wv.x;
                acc[mi][1] += wv.y;
                acc[mi][2] += wv.z;
                acc[mi][3] += wv.w;
                ++c;
            }
            cur[mi] = c;
        }
    }

    // ---- epilogue: bias + store ----
    const int gn = n0 + lane4;
    if (gn < HID) {
        const float4 b = *reinterpret_cast<const float4*>(bias + gn);
        #pragma unroll
        for (int mi = 0; mi < 16; ++mi) {
            float4 v;
            v.x = acc[mi][0] + b.x;
            v.y = acc[mi][1] + b.y;
            v.z = acc[mi][2] + b.z;
            v.w = acc[mi][3] + b.w;
            *reinterpret_cast<float4*>(C + (size_t)(m0w + mi) * HID + gn) = v;
        }
    }
}

// ===========================================================================
// Dense SIMT SGEMM (NT) for layer 1 — R4 version (proven bitwise, at FFMA
// roofline). C[M,N] = A[M,K] @ W[N,K]^T + bias[N]. BK=16.
// ===========================================================================
template<int BK>
__global__ __launch_bounds__(256, 2)
void sgemm_nt(const float* __restrict__ A, const float* __restrict__ W,
              const float* __restrict__ bias, float* __restrict__ C,
              int M, int N, int K)
{
    constexpr int QPR    = BK / 4;
    constexpr int ROWSPP = 256 / QPR;
    constexpr int NQ     = BK / 8;
    constexpr int HQ     = NQ / 2;

    extern __shared__ float sm[];
    float* As = sm;
    float* Ws = sm + 2 * BK * 128;

    const int tid = threadIdx.x;
    const int tx  = tid & 15;
    const int ty  = tid >> 4;
    const int m0  = blockIdx.y * 128;
    const int n0  = blockIdx.x * 128;

    const int ldCol = (tid % QPR) * 4;
    const int ldRow = tid / QPR;

    float acc[8][8];
    #pragma unroll
    for (int i = 0; i < 8; ++i)
        #pragma unroll
        for (int j = 0; j < 8; ++j) acc[i][j] = 0.0f;

    const int numTiles = K / BK;
    const float4 z4 = make_float4(0.f, 0.f, 0.f, 0.f);

    #pragma unroll
    for (int p = 0; p < NQ; ++p) {
        const int r  = ldRow + p * ROWSPP;
        const float4 av = *reinterpret_cast<const float4*>(A + (size_t)(m0 + r) * K + ldCol);
        const int wn = n0 + r;
        const float4 wv = (wn < N)
            ? *reinterpret_cast<const float4*>(W + (size_t)wn * K + ldCol) : z4;
        #pragma unroll
        for (int q = 0; q < 4; ++q) {
            As[(ldCol + q) * 128 + r] = (&av.x)[q];
            Ws[(ldCol + q) * 128 + r] = (&wv.x)[q];
        }
    }
    __syncthreads();

    for (int t = 0; t < numTiles; ++t) {
        const int  buf     = t & 1;
        const int  nb      = buf ^ 1;
        const bool hasNext = (t + 1 < numTiles);
        const int  kn      = (t + 1) * BK;

        float* Ab = As + buf * BK * 128;
        float* Wb = Ws + buf * BK * 128;
        float* An = As + nb * BK * 128;
        float* Wn = Ws + nb * BK * 128;

        float4 pa[HQ], pw[HQ];

        if (hasNext) {
            #pragma unroll
            for (int p = 0; p < HQ; ++p) {
                const int r = ldRow + p * ROWSPP;
                pa[p] = *reinterpret_cast<const float4*>(A + (size_t)(m0 + r) * K + kn + ldCol);
                const int wn = n0 + r;
                pw[p] = (wn < N)
                    ? *reinterpret_cast<const float4*>(W + (size_t)wn * K + kn + ldCol) : z4;
            }
        }
        #pragma unroll
        for (int kk = 0; kk < BK / 2; ++kk) {
            float af[8], wf[8];
            *reinterpret_cast<float4*>(&af[0]) = *reinterpret_cast<const float4*>(Ab + kk * 128 + ty * 8);
            *reinterpret_cast<float4*>(&af[4]) = *reinterpret_cast<const float4*>(Ab + kk * 128 + ty * 8 + 4);
            *reinterpret_cast<float4*>(&wf[0]) = *reinterpret_cast<const float4*>(Wb + kk * 128 + tx * 4);
            *reinterpret_cast<float4*>(&wf[4]) = *reinterpret_cast<const float4*>(Wb + kk * 128 + 64 + tx * 4);
            #pragma unroll
            for (int i = 0; i < 8; ++i)
                #pragma unroll
                for (int j = 0; j < 8; ++j)
                    acc[i][j] += af[i] * wf[j];
        }
        if (hasNext) {
            #pragma unroll
            for (int p = 0; p < HQ; ++p) {
                const int r = ldRow + p * ROWSPP;
                #pragma unroll
                for (int q = 0; q < 4; ++q) {
                    An[(ldCol + q) * 128 + r] = (&pa[p].x)[q];
                    Wn[(ldCol + q) * 128 + r] = (&pw[p].x)[q];
                }
            }
            #pragma unroll
            for (int p = 0; p < HQ; ++p) {
                const int r = ldRow + (HQ + p) * ROWSPP;
                pa[p] = *reinterpret_cast<const float4*>(A + (size_t)(m0 + r) * K + kn + ldCol);
                const int wn = n0 + r;
                pw[p] = (wn < N)
                    ? *reinterpret_cast<const float4*>(W + (size_t)wn * K + kn + ldCol) : z4;
            }
        }
        #pragma unroll
        for (int kk = BK / 2; kk < BK; ++kk) {
            float af[8], wf[8];
            *reinterpret_cast<float4*>(&af[0]) = *reinterpret_cast<const float4*>(Ab + kk * 128 + ty * 8);
            *reinterpret_cast<float4*>(&af[4]) = *reinterpret_cast<const float4*>(Ab + kk * 128 + ty * 8 + 4);
            *reinterpret_cast<float4*>(&wf[0]) = *reinterpret_cast<const float4*>(Wb + kk * 128 + tx * 4);
            *reinterpret_cast<float4*>(&wf[4]) = *reinterpret_cast<const float4*>(Wb + kk * 128 + 64 + tx * 4);
            #pragma unroll
            for (int i = 0; i < 8; ++i)
                #pragma unroll
                for (int j = 0; j < 8; ++j)
                    acc[i][j] += af[i] * wf[j];
        }
        if (hasNext) {
            #pragma unroll
            for (int p = 0; p < HQ; ++p) {
                const int r = ldRow + (HQ + p) * ROWSPP;
                #pragma unroll
                for (int q = 0; q < 4; ++q) {
                    An[(ldCol + q) * 128 + r] = (&pa[p].x)[q];
                    Wn[(ldCol + q) * 128 + r] = (&pw[p].x)[q];
                }
            }
            __syncthreads();
        }
    }

    #pragma unroll
    for (int i = 0; i < 8; ++i) {
        const int m = m0 + ty * 8 + i;
        {
            const int n = n0 + tx * 4;
            if (n < N) {
                float4 v;
                v.x = acc[i][0] + bias[n + 0];
                v.y = acc[i][1] + bias[n + 1];
                v.z = acc[i][2] + bias[n + 2];
                v.w = acc[i][3] + bias[n + 3];
                *reinterpret_cast<float4*>(C + (size_t)m * N + n) = v;
            }
        }
        {
            const int n = n0 + 64 + tx * 4;
            if (n < N) {
                float4 v;
                v.x = acc[i][4] + bias[n + 0];
                v.y = acc[i][5] + bias[n + 1];
                v.z = acc[i][6] + bias[n + 2];
                v.w = acc[i][7] + bias[n + 3];
                *reinterpret_cast<float4*>(C + (size_t)m * N + n) = v;
            }
        }
    }
}

// ===========================================================================
// LIF recurrence, float4-vectorized (component-wise, bitwise identical).
// ===========================================================================
__global__ void lif_kernel4(const float4* __restrict__ cur,
                            float4* __restrict__ spk,
                            const float* __restrict__ beta_ptr, int BH4)
{
    const int idx = blockIdx.x * blockDim.x + threadIdx.x;
    if (idx >= BH4) return;
    const float beta = fminf(fmaxf(beta_ptr[0], 0.0f), 1.0f);
    float4 mem = make_float4(0.f, 0.f, 0.f, 0.f);
    float4 rst = make_float4(0.f, 0.f, 0.f, 0.f);
    #pragma unroll
    for (int t = 0; t < T_STEPS; ++t) {
        const float4 c = cur[(size_t)t * BH4 + idx];
        float4 s;
        mem.x = beta * mem.x + c.x - rst.x; s.x = (mem.x - 1.0f > 0.0f) ? 1.0f : 0.0f;
        mem.y = beta * mem.y + c.y - rst.y; s.y = (mem.y - 1.0f > 0.0f) ? 1.0f : 0.0f;
        mem.z = beta * mem.z + c.z - rst.z; s.z = (mem.z - 1.0f > 0.0f) ? 1.0f : 0.0f;
        mem.w = beta * mem.w + c.w - rst.w; s.w = (mem.w - 1.0f > 0.0f) ? 1.0f : 0.0f;
        spk[(size_t)t * BH4 + idx] = s;
        rst = s;
    }
}

__global__ __launch_bounds__(256)
void gemm3_kernel(const float* __restrict__ S2, const float* __restrict__ W3,
                  const float* __restrict__ b3, float* __restrict__ C3, int M)
{
    __shared__ float w3s[NOUT * HID];
    for (int i = threadIdx.x; i < NOUT * HID; i += 256) w3s[i] = W3[i];
    __syncthreads();

    const int warp = threadIdx.x >> 5;
    const int lane = threadIdx.x & 31;
    const int row  = blockIdx.x * 8 + warp;
    if (row >= M) return;

    const float* s = S2 + (size_t)row * HID;
    float sv[HID / 32];
    #pragma unroll
    for (int i = 0; i < HID / 32; ++i) sv[i] = s[lane + i * 32];

    float accv[NOUT];
    #pragma unroll
    for (int o = 0; o < NOUT; ++o) {
        float a = 0.0f;
        #pragma unroll
        for (int i = 0; i < HID / 32; ++i)
            a += sv[i] * w3s[o * HID + lane + i * 32];
        accv[o] = a;
    }
    #pragma unroll
    for (int o = 0; o < NOUT; ++o) {
        float v = accv[o];
        #pragma unroll
        for (int off = 16; off > 0; off >>= 1)
            v += __shfl_down_sync(0xffffffffu, v, off);
        if (lane == 0) C3[(size_t)row * NOUT + o] = v + b3[o];
    }
}

__global__ void lif3_kernel(const float* __restrict__ C3,
                            float* __restrict__ s3r, float* __restrict__ out,
                            const float* __restrict__ beta_ptr)
{
    const int idx = blockIdx.x * blockDim.x + threadIdx.x;
    if (idx >= BATCH * NOUT) return;
    const float beta = fminf(fmaxf(beta_ptr[0], 0.0f), 1.0f);
    float mem = 0.0f, rst = 0.0f, sum = 0.0f;
    #pragma unroll
    for (int t = 0; t < T_STEPS; ++t) {
        const float c = C3[(size_t)t * BATCH * NOUT + idx];
        mem = beta * mem + c - rst;
        const float s = (mem - 1.0f > 0.0f) ? 1.0f : 0.0f;
        s3r[(size_t)t * BATCH * NOUT + idx] = s;
        sum += s;
        rst = s;
    }
    out[idx] = sum;
}

// ===========================================================================
extern "C" void kernel_launch(void* const* d_in, const int* in_sizes, int n_in,
                              void* d_out, int out_size)
{
    const float* x     = (const float*)d_in[0];
    const float* W1    = (const float*)d_in[1];
    const float* b1    = (const float*)d_in[2];
    const float* W2    = (const float*)d_in[3];
    const float* b2    = (const float*)d_in[4];
    const float* W3    = (const float*)d_in[5];
    const float* b3    = (const float*)d_in[6];
    const float* beta1 = (const float*)d_in[7];
    const float* beta2 = (const float*)d_in[8];
    const float* beta3 = (const float*)d_in[9];

    float* out = (float*)d_out;
    float* s1r = out + (size_t)BATCH * NOUT;
    float* s2r = s1r + (size_t)M_ROWS * HID;
    float* s3r = s2r + (size_t)M_ROWS * HID;

    float *c1, *c2, *c3, *w2t;
    unsigned short* klist;
    int* kcount;
    cudaGetSymbolAddress((void**)&c1, g_c1);
    cudaGetSymbolAddress((void**)&c2, g_c2);
    cudaGetSymbolAddress((void**)&c3, g_c3);
    cudaGetSymbolAddress((void**)&w2t, g_w2t);
    cudaGetSymbolAddress((void**)&klist, g_klist);
    cudaGetSymbolAddress((void**)&kcount, g_kcount);

    constexpr int SM16 = 4 * 16 * 128 * 4;   // 32 KB
    static bool attr_set = false;
    if (!attr_set) {
        cudaFuncSetAttribute(sgemm_nt<16>, cudaFuncAttributeMaxDynamicSharedMemorySize, SM16);
        attr_set = true;
    }

    const int BH  = BATCH * HID;   // 409600
    const int BH4 = BH / 4;
    const dim3 grid((HID + 127) / 128, M_ROWS / 128);

    // 0) W2 -> W2T (independent of GEMM1; pure data movement)
    {
        dim3 tg(HID / 32, HID / 32);
        transpose_w2<<<tg, dim3(32, 8)>>>(W2, w2t);
    }

    // 1) C1 = X @ W1^T + b1   (dense scalar SGEMM, K=784, BK=16)
    sgemm_nt<16><<<grid, 256, SM16>>>(x, W1, b1, c1, M_ROWS, HID, DIN);

    // 2) LIF1 -> s1r
    lif_kernel4<<<(BH4 + 255) / 256, 256>>>((const float4*)c1, (float4*)s1r, beta1, BH4);

    // 3a) active-k lists from s1r
    build_klist<<<M_ROWS / 8, 256>>>(s1r, klist, kcount);

    // 3b) sparse GEMM2: C2 = S1 @ W2^T + b2 (bitwise-exact zero skipping)
    {
        dim3 sg(NBLK, M_ROWS / 128);
        gemm2_sparse<<<sg, 256>>>(klist, kcount, w2t, b2, c2);
    }

    // 4) LIF2 -> s2r
    lif_kernel4<<<(BH4 + 255) / 256, 256>>>((const float4*)c2, (float4*)s2r, beta2, BH4);

    // 5) C3 = S2 @ W3^T + b3
    gemm3_kernel<<<M_ROWS / 8, 256>>>(s2r, W3, b3, c3, M_ROWS);

    // 6) LIF3 + sum
    lif3_kernel<<<(BATCH * NOUT + 255) / 256, 256>>>(c3, s3r, out, beta3);
}

// round 7
// speedup vs baseline: 1.5579x; 1.0719x over previous
#include <cuda_runtime.h>
#include <cstdint>

// ---------------------------------------------------------------------------
// ActivityDecaySNN: 3-layer LIF SNN forward. T=50, B=512, 784->800->800->10.
// BITWISE CONSTRAINT: currents must reproduce the reference's ascending-k fp32
// FMA chain per element. GEMM1: scalar SIMT SGEMM (at FFMA issue roofline).
// GEMM2: binary-spike input -> skipping zero terms is bitwise exact -> sparse
// ascending gather of W2T rows via padded u8 k-lists (branch-free batches of 8,
// sentinel k=80 hits a zeroed smem row: acc += +0.0 is a bitwise identity).
// d_out: out[512*10] | s1r[50*512*800] | s2r[50*512*800] | s3r[50*512*10]
// ---------------------------------------------------------------------------

#define T_STEPS 50
#define BATCH   512
#define DIN     784
#define HID     800
#define NOUT    10
#define M_ROWS  (T_STEPS * BATCH)   // 25600
#define SBK     80                  // k-rows per tile
#define NTILES  10                  // 800 / 80

__device__ float  g_c1[(size_t)M_ROWS * HID];
__device__ float  g_c2[(size_t)M_ROWS * HID];
__device__ float  g_c3[(size_t)M_ROWS * NOUT];
__device__ float  g_w2t[(size_t)HID * HID];              // W2 transposed [k][n]
__device__ uint8_t g_klist[(size_t)M_ROWS * HID];        // segmented u8 lists
__device__ int    g_kcount[M_ROWS * NTILES];

// ===========================================================================
// W2 transpose: W2T[k][n] = W2[n][k]. 32x32 tiles.
// ===========================================================================
__global__ void transpose_w2(const float* __restrict__ W, float* __restrict__ WT)
{
    __shared__ float t[32][33];
    const int bx = blockIdx.x * 32, by = blockIdx.y * 32;
    #pragma unroll
    for (int r = 0; r < 4; ++r)
        t[threadIdx.y + r * 8][threadIdx.x] =
            W[(size_t)(by + threadIdx.y + r * 8) * HID + bx + threadIdx.x];
    __syncthreads();
    #pragma unroll
    for (int r = 0; r < 4; ++r)
        WT[(size_t)(bx + threadIdx.y + r * 8) * HID + by + threadIdx.x] =
            t[threadIdx.x][threadIdx.y + r * 8];
}

// ===========================================================================
// Build segmented u8 k-lists (local k within each 80-row tile, ascending),
// padded with sentinel 80 up to the next multiple of 8 (capacity 80 per tile).
// One warp per row m.
// ===========================================================================
__global__ __launch_bounds__(256)
void build_klist(const float* __restrict__ spk,
                 uint8_t* __restrict__ klist, int* __restrict__ kcount)
{
    const int m    = blockIdx.x * 8 + (threadIdx.x >> 5);
    const int lane = threadIdx.x & 31;
    const float* row = spk + (size_t)m * HID;
    uint8_t* kl = klist + (size_t)m * HID;

    #pragma unroll
    for (int t = 0; t < NTILES; ++t) {
        int base = 0;
        #pragma unroll
        for (int j = 0; j < SBK; j += 32) {
            const int kloc  = j + lane;
            const bool act  = (kloc < SBK) && (row[t * SBK + kloc] > 0.5f);
            const unsigned mask = __ballot_sync(0xffffffffu, act);
            if (act)
                kl[t * SBK + base + __popc(mask & ((1u << lane) - 1u))] = (uint8_t)kloc;
            base += __popc(mask);
        }
        // pad to multiple of 8 with sentinel (maps to zeroed smem row)
        const int padUp = min((base + 7) & ~7, SBK);
        const int idx   = base + lane;
        if (idx < padUp) kl[t * SBK + idx] = (uint8_t)SBK;
        if (lane == 0) kcount[m * NTILES + t] = base;
    }
}

// ===========================================================================
// Sparse GEMM2: C2[m,n] = b2[n] + sum_{k active(m), ascending} W2T[k][n]
// Block: 128 m x 128 n; 8 warps, warp owns 16 m-rows (uniform lists -> no
// divergence). W2T staged in 80-row tiles + 1 zero sentinel row (41.5 KB).
// Inner loop: branch-free batches of 8 k's (one LDG.64 -> 8 indep LDS.128).
// ===========================================================================
__global__ __launch_bounds__(256, 2)
void gemm2_sparse(const uint8_t* __restrict__ klist,
                  const int* __restrict__ kcount,
                  const float* __restrict__ WT,
                  const float* __restrict__ bias, float* __restrict__ C)
{
    __shared__ float wt[(SBK + 1) * 128];   // +1 = zero sentinel row (row 80)

    const int tid   = threadIdx.x;
    const int warp  = tid >> 5;
    const int lane  = tid & 31;
    const int n0    = blockIdx.x * 128;
    const int m0w   = blockIdx.y * 128 + warp * 16;
    const int lane4 = lane * 4;

    // zero the sentinel row once (never touched by staging)
    if (tid < 32)
        *reinterpret_cast<float4*>(&wt[SBK * 128 + tid * 4]) =
            make_float4(0.f, 0.f, 0.f, 0.f);

    float acc[16][4];
    #pragma unroll
    for (int mi = 0; mi < 16; ++mi)
        #pragma unroll
        for (int j = 0; j < 4; ++j) acc[mi][j] = 0.0f;

#define ADD1(WRD, SH)                                                         \
    {                                                                         \
        const int k_ = ((WRD) >> (SH)) & 0xFF;                                \
        const float4 wv_ = *reinterpret_cast<const float4*>(                  \
            &wt[k_ * 128 + lane4]);                                           \
        acc[mi][0] += wv_.x; acc[mi][1] += wv_.y;                             \
        acc[mi][2] += wv_.z; acc[mi][3] += wv_.w;                             \
    }

    for (int t = 0; t < NTILES; ++t) {
        __syncthreads();   // protect previous tile (and sentinel init) ordering
        // ---- stage W2T[t*80 : t*80+80, n0 : n0+128) ----
        #pragma unroll
        for (int p = 0; p < SBK * 32 / 256; ++p) {        // 10 passes
            const int i   = tid + p * 256;
            const int row = i >> 5, c4 = i & 31;
            const int gn  = n0 + c4 * 4;
            const float4 v = (gn < HID)
                ? *reinterpret_cast<const float4*>(WT + (size_t)(t * SBK + row) * HID + gn)
                : make_float4(0.f, 0.f, 0.f, 0.f);
            *reinterpret_cast<float4*>(&wt[row * 128 + c4 * 4]) = v;
        }
        __syncthreads();

        #pragma unroll
        for (int mi = 0; mi < 16; ++mi) {
            const int m   = m0w + mi;
            const int cnt = __ldg(kcount + m * NTILES + t);
            const uint2* klp = reinterpret_cast<const uint2*>(
                klist + (size_t)m * HID + t * SBK);
            const int nbatch = (cnt + 7) >> 3;
            for (int b = 0; b < nbatch; ++b) {
                const uint2 kv = __ldg(klp + b);
                ADD1(kv.x, 0)  ADD1(kv.x, 8)  ADD1(kv.x, 16) ADD1(kv.x, 24)
                ADD1(kv.y, 0)  ADD1(kv.y, 8)  ADD1(kv.y, 16) ADD1(kv.y, 24)
            }
        }
    }
#undef ADD1

    // ---- epilogue: bias + store ----
    const int gn = n0 + lane4;
    if (gn < HID) {
        const float4 b = *reinterpret_cast<const float4*>(bias + gn);
        #pragma unroll
        for (int mi = 0; mi < 16; ++mi) {
            float4 v;
            v.x = acc[mi][0] + b.x;
            v.y = acc[mi][1] + b.y;
            v.z = acc[mi][2] + b.z;
            v.w = acc[mi][3] + b.w;
            *reinterpret_cast<float4*>(C + (size_t)(m0w + mi) * HID + gn) = v;
        }
    }
}

// ===========================================================================
// Dense SIMT SGEMM (NT) for layer 1 — R4 version (bitwise, at FFMA roofline).
// ===========================================================================
template<int BK>
__global__ __launch_bounds__(256, 2)
void sgemm_nt(const float* __restrict__ A, const float* __restrict__ W,
              const float* __restrict__ bias, float* __restrict__ C,
              int M, int N, int K)
{
    constexpr int QPR    = BK / 4;
    constexpr int ROWSPP = 256 / QPR;
    constexpr int NQ     = BK / 8;
    constexpr int HQ     = NQ / 2;

    extern __shared__ float sm[];
    float* As = sm;
    float* Ws = sm + 2 * BK * 128;

    const int tid = threadIdx.x;
    const int tx  = tid & 15;
    const int ty  = tid >> 4;
    const int m0  = blockIdx.y * 128;
    const int n0  = blockIdx.x * 128;

    const int ldCol = (tid % QPR) * 4;
    const int ldRow = tid / QPR;

    float acc[8][8];
    #pragma unroll
    for (int i = 0; i < 8; ++i)
        #pragma unroll
        for (int j = 0; j < 8; ++j) acc[i][j] = 0.0f;

    const int numTiles = K / BK;
    const float4 z4 = make_float4(0.f, 0.f, 0.f, 0.f);

    #pragma unroll
    for (int p = 0; p < NQ; ++p) {
        const int r  = ldRow + p * ROWSPP;
        const float4 av = *reinterpret_cast<const float4*>(A + (size_t)(m0 + r) * K + ldCol);
        const int wn = n0 + r;
        const float4 wv = (wn < N)
            ? *reinterpret_cast<const float4*>(W + (size_t)wn * K + ldCol) : z4;
        #pragma unroll
        for (int q = 0; q < 4; ++q) {
            As[(ldCol + q) * 128 + r] = (&av.x)[q];
            Ws[(ldCol + q) * 128 + r] = (&wv.x)[q];
        }
    }
    __syncthreads();

    for (int t = 0; t < numTiles; ++t) {
        const int  buf     = t & 1;
        const int  nb      = buf ^ 1;
        const bool hasNext = (t + 1 < numTiles);
        const int  kn      = (t + 1) * BK;

        float* Ab = As + buf * BK * 128;
        float* Wb = Ws + buf * BK * 128;
        float* An = As + nb * BK * 128;
        float* Wn = Ws + nb * BK * 128;

        float4 pa[HQ], pw[HQ];

        if (hasNext) {
            #pragma unroll
            for (int p = 0; p < HQ; ++p) {
                const int r = ldRow + p * ROWSPP;
                pa[p] = *reinterpret_cast<const float4*>(A + (size_t)(m0 + r) * K + kn + ldCol);
                const int wn = n0 + r;
                pw[p] = (wn < N)
                    ? *reinterpret_cast<const float4*>(W + (size_t)wn * K + kn + ldCol) : z4;
            }
        }
        #pragma unroll
        for (int kk = 0; kk < BK / 2; ++kk) {
            float af[8], wf[8];
            *reinterpret_cast<float4*>(&af[0]) = *reinterpret_cast<const float4*>(Ab + kk * 128 + ty * 8);
            *reinterpret_cast<float4*>(&af[4]) = *reinterpret_cast<const float4*>(Ab + kk * 128 + ty * 8 + 4);
            *reinterpret_cast<float4*>(&wf[0]) = *reinterpret_cast<const float4*>(Wb + kk * 128 + tx * 4);
            *reinterpret_cast<float4*>(&wf[4]) = *reinterpret_cast<const float4*>(Wb + kk * 128 + 64 + tx * 4);
            #pragma unroll
            for (int i = 0; i < 8; ++i)
                #pragma unroll
                for (int j = 0; j < 8; ++j)
                    acc[i][j] += af[i] * wf[j];
        }
        if (hasNext) {
            #pragma unroll
            for (int p = 0; p < HQ; ++p) {
                const int r = ldRow + p * ROWSPP;
                #pragma unroll
                for (int q = 0; q < 4; ++q) {
                    An[(ldCol + q) * 128 + r] = (&pa[p].x)[q];
                    Wn[(ldCol + q) * 128 + r] = (&pw[p].x)[q];
                }
            }
            #pragma unroll
            for (int p = 0; p < HQ; ++p) {
                const int r = ldRow + (HQ + p) * ROWSPP;
                pa[p] = *reinterpret_cast<const float4*>(A + (size_t)(m0 + r) * K + kn + ldCol);
                const int wn = n0 + r;
                pw[p] = (wn < N)
                    ? *reinterpret_cast<const float4*>(W + (size_t)wn * K + kn + ldCol) : z4;
            }
        }
        #pragma unroll
        for (int kk = BK / 2; kk < BK; ++kk) {
            float af[8], wf[8];
            *reinterpret_cast<float4*>(&af[0]) = *reinterpret_cast<const float4*>(Ab + kk * 128 + ty * 8);
            *reinterpret_cast<float4*>(&af[4]) = *reinterpret_cast<const float4*>(Ab + kk * 128 + ty * 8 + 4);
            *reinterpret_cast<float4*>(&wf[0]) = *reinterpret_cast<const float4*>(Wb + kk * 128 + tx * 4);
            *reinterpret_cast<float4*>(&wf[4]) = *reinterpret_cast<const float4*>(Wb + kk * 128 + 64 + tx * 4);
            #pragma unroll
            for (int i = 0; i < 8; ++i)
                #pragma unroll
                for (int j = 0; j < 8; ++j)
                    acc[i][j] += af[i] * wf[j];
        }
        if (hasNext) {
            #pragma unroll
            for (int p = 0; p < HQ; ++p) {
                const int r = ldRow + (HQ + p) * ROWSPP;
                #pragma unroll
                for (int q = 0; q < 4; ++q) {
                    An[(ldCol + q) * 128 + r] = (&pa[p].x)[q];
                    Wn[(ldCol + q) * 128 + r] = (&pw[p].x)[q];
                }
            }
            __syncthreads();
        }
    }

    #pragma unroll
    for (int i = 0; i < 8; ++i) {
        const int m = m0 + ty * 8 + i;
        {
            const int n = n0 + tx * 4;
            if (n < N) {
                float4 v;
                v.x = acc[i][0] + bias[n + 0];
                v.y = acc[i][1] + bias[n + 1];
                v.z = acc[i][2] + bias[n + 2];
                v.w = acc[i][3] + bias[n + 3];
                *reinterpret_cast<float4*>(C + (size_t)m * N + n) = v;
            }
        }
        {
            const int n = n0 + 64 + tx * 4;
            if (n < N) {
                float4 v;
                v.x = acc[i][4] + bias[n + 0];
                v.y = acc[i][5] + bias[n + 1];
                v.z = acc[i][6] + bias[n + 2];
                v.w = acc[i][7] + bias[n + 3];
                *reinterpret_cast<float4*>(C + (size_t)m * N + n) = v;
            }
        }
    }
}

// ===========================================================================
// LIF recurrence, float4-vectorized (component-wise, bitwise identical).
// ===========================================================================
__global__ void lif_kernel4(const float4* __restrict__ cur,
                            float4* __restrict__ spk,
                            const float* __restrict__ beta_ptr, int BH4)
{
    const int idx = blockIdx.x * blockDim.x + threadIdx.x;
    if (idx >= BH4) return;
    const float beta = fminf(fmaxf(beta_ptr[0], 0.0f), 1.0f);
    float4 mem = make_float4(0.f, 0.f, 0.f, 0.f);
    float4 rst = make_float4(0.f, 0.f, 0.f, 0.f);
    #pragma unroll
    for (int t = 0; t < T_STEPS; ++t) {
        const float4 c = cur[(size_t)t * BH4 + idx];
        float4 s;
        mem.x = beta * mem.x + c.x - rst.x; s.x = (mem.x - 1.0f > 0.0f) ? 1.0f : 0.0f;
        mem.y = beta * mem.y + c.y - rst.y; s.y = (mem.y - 1.0f > 0.0f) ? 1.0f : 0.0f;
        mem.z = beta * mem.z + c.z - rst.z; s.z = (mem.z - 1.0f > 0.0f) ? 1.0f : 0.0f;
        mem.w = beta * mem.w + c.w - rst.w; s.w = (mem.w - 1.0f > 0.0f) ? 1.0f : 0.0f;
        spk[(size_t)t * BH4 + idx] = s;
        rst = s;
    }
}

__global__ __launch_bounds__(256)
void gemm3_kernel(const float* __restrict__ S2, const float* __restrict__ W3,
                  const float* __restrict__ b3, float* __restrict__ C3, int M)
{
    __shared__ float w3s[NOUT * HID];
    for (int i = threadIdx.x; i < NOUT * HID; i += 256) w3s[i] = W3[i];
    __syncthreads();

    const int warp = threadIdx.x >> 5;
    const int lane = threadIdx.x & 31;
    const int row  = blockIdx.x * 8 + warp;
    if (row >= M) return;

    const float* s = S2 + (size_t)row * HID;
    float sv[HID / 32];
    #pragma unroll
    for (int i = 0; i < HID / 32; ++i) sv[i] = s[lane + i * 32];

    float accv[NOUT];
    #pragma unroll
    for (int o = 0; o < NOUT; ++o) {
        float a = 0.0f;
        #pragma unroll
        for (int i = 0; i < HID / 32; ++i)
            a += sv[i] * w3s[o * HID + lane + i * 32];
        accv[o] = a;
    }
    #pragma unroll
    for (int o = 0; o < NOUT; ++o) {
        float v = accv[o];
        #pragma unroll
        for (int off = 16; off > 0; off >>= 1)
            v += __shfl_down_sync(0xffffffffu, v, off);
        if (lane == 0) C3[(size_t)row * NOUT + o] = v + b3[o];
    }
}

__global__ void lif3_kernel(const float* __restrict__ C3,
                            float* __restrict__ s3r, float* __restrict__ out,
                            const float* __restrict__ beta_ptr)
{
    const int idx = blockIdx.x * blockDim.x + threadIdx.x;
    if (idx >= BATCH * NOUT) return;
    const float beta = fminf(fmaxf(beta_ptr[0], 0.0f), 1.0f);
    float mem = 0.0f, rst = 0.0f, sum = 0.0f;
    #pragma unroll
    for (int t = 0; t < T_STEPS; ++t) {
        const float c = C3[(size_t)t * BATCH * NOUT + idx];
        mem = beta * mem + c - rst;
        const float s = (mem - 1.0f > 0.0f) ? 1.0f : 0.0f;
        s3r[(size_t)t * BATCH * NOUT + idx] = s;
        sum += s;
        rst = s;
    }
    out[idx] = sum;
}

// ===========================================================================
extern "C" void kernel_launch(void* const* d_in, const int* in_sizes, int n_in,
                              void* d_out, int out_size)
{
    const float* x     = (const float*)d_in[0];
    const float* W1    = (const float*)d_in[1];
    const float* b1    = (const float*)d_in[2];
    const float* W2    = (const float*)d_in[3];
    const float* b2    = (const float*)d_in[4];
    const float* W3    = (const float*)d_in[5];
    const float* b3    = (const float*)d_in[6];
    const float* beta1 = (const float*)d_in[7];
    const float* beta2 = (const float*)d_in[8];
    const float* beta3 = (const float*)d_in[9];

    float* out = (float*)d_out;
    float* s1r = out + (size_t)BATCH * NOUT;
    float* s2r = s1r + (size_t)M_ROWS * HID;
    float* s3r = s2r + (size_t)M_ROWS * HID;

    float *c1, *c2, *c3, *w2t;
    uint8_t* klist;
    int* kcount;
    cudaGetSymbolAddress((void**)&c1, g_c1);
    cudaGetSymbolAddress((void**)&c2, g_c2);
    cudaGetSymbolAddress((void**)&c3, g_c3);
    cudaGetSymbolAddress((void**)&w2t, g_w2t);
    cudaGetSymbolAddress((void**)&klist, g_klist);
    cudaGetSymbolAddress((void**)&kcount, g_kcount);

    constexpr int SM16 = 4 * 16 * 128 * 4;   // 32 KB
    static bool attr_set = false;
    if (!attr_set) {
        cudaFuncSetAttribute(sgemm_nt<16>, cudaFuncAttributeMaxDynamicSharedMemorySize, SM16);
        attr_set = true;
    }

    const int BH  = BATCH * HID;   // 409600
    const int BH4 = BH / 4;
    const dim3 grid((HID + 127) / 128, M_ROWS / 128);

    // 0) W2 -> W2T (overlaps conceptually with GEMM1 queueing; pure data move)
    {
        dim3 tg(HID / 32, HID / 32);
        transpose_w2<<<tg, dim3(32, 8)>>>(W2, w2t);
    }

    // 1) C1 = X @ W1^T + b1   (dense scalar SGEMM, K=784, BK=16)
    sgemm_nt<16><<<grid, 256, SM16>>>(x, W1, b1, c1, M_ROWS, HID, DIN);

    // 2) LIF1 -> s1r
    lif_kernel4<<<(BH4 + 255) / 256, 256>>>((const float4*)c1, (float4*)s1r, beta1, BH4);

    // 3a) segmented padded u8 k-lists from s1r
    build_klist<<<M_ROWS / 8, 256>>>(s1r, klist, kcount);

    // 3b) sparse GEMM2: C2 = S1 @ W2^T + b2 (bitwise-exact, branch-free inner)
    {
        dim3 sg((HID + 127) / 128, M_ROWS / 128);
        gemm2_sparse<<<sg, 256>>>(klist, kcount, w2t, b2, c2);
    }

    // 4) LIF2 -> s2r
    lif_kernel4<<<(BH4 + 255) / 256, 256>>>((const float4*)c2, (float4*)s2r, beta2, BH4);

    // 5) C3 = S2 @ W3^T + b3
    gemm3_kernel<<<M_ROWS / 8, 256>>>(s2r, W3, b3, c3, M_ROWS);

    // 6) LIF3 + sum
    lif3_kernel<<<(BATCH * NOUT + 255) / 256, 256>>>(c3, s3r, out, beta3);
}